// round 8
// baseline (speedup 1.0000x reference)
#include <cuda_runtime.h>

#define BB 64      // batch
#define SS 512     // sequence length
#define EE 256     // embedding dim
#define HH 512     // hidden
#define GG 2048    // 4*H gate rows

typedef unsigned long long u64;
typedef unsigned int u32;

// ---------------------------------------------------------------------------
// Device globals
// ---------------------------------------------------------------------------
__device__ u32 g_wf[128];                     // per-CTA h write-flags (monotonic)
__device__ float g_xg[SS * GG * BB];          // x_gates [s][g][b]
__device__ float g_h[4][HH * BB];             // h ring: slot s&3 = h(s), [k][b]

// ---------------------------------------------------------------------------
// f32x2 helpers (packed FFMA2/FADD2 -- only reachable via PTX)
// ---------------------------------------------------------------------------
__device__ __forceinline__ u64 fma2(u64 a, u64 b, u64 c) {
    u64 d; asm("fma.rn.f32x2 %0, %1, %2, %3;" : "=l"(d) : "l"(a), "l"(b), "l"(c)); return d;
}
__device__ __forceinline__ u64 add2(u64 a, u64 b) {
    u64 d; asm("add.rn.f32x2 %0, %1, %2;" : "=l"(d) : "l"(a), "l"(b)); return d;
}
__device__ __forceinline__ u64 pack2(float x, float y) {
    u64 d; asm("mov.b64 %0, {%1, %2};" : "=l"(d) : "f"(x), "f"(y)); return d;
}
__device__ __forceinline__ float2 unpack2(u64 v) {
    float2 r; asm("mov.b64 {%0, %1}, %2;" : "=f"(r.x), "=f"(r.y) : "l"(v)); return r;
}
__device__ __forceinline__ float sigf(float x) { return 1.f / (1.f + __expf(-x)); }
__device__ __forceinline__ float tanh_f(float x) { return 2.f / (1.f + __expf(-2.f * x)) - 1.f; }

// ---------------------------------------------------------------------------
// Phase A: x_gates[s][g][b] = emb[seq[b][s]] . W_ih[g] + b_ih[g] + b_hh[g]
// 128x64 tile, BK=16, 8Mx4N f32x2 micro. Register-staged double buffering:
// next tile's LDGs issue before current tile's compute (latency hidden).
// xg stores use streaming policy (st.cs) to keep L2 for the h ring.
// ---------------------------------------------------------------------------
__global__ void __launch_bounds__(256) xgates_gemm(
    const void* __restrict__ seq,
    const float* __restrict__ emb,
    const float* __restrict__ Wih,
    const float* __restrict__ bih,
    const float* __restrict__ bhh)
{
    __shared__ float  As[16][132];
    __shared__ float2 Bs2[16][66];
    __shared__ int rows[128];
    __shared__ int s_is64;

    const int tid = threadIdx.x;
    const int s0 = blockIdx.y * 2;
    const int g0 = blockIdx.x * 64;

    if (tid == 0) s_is64 = 1;
    __syncthreads();
    if (tid < 64) {
        if (((const u32*)seq)[2 * tid + 1] != 0u) s_is64 = 0;
    }
    __syncthreads();
    if (tid < 128) {
        int b = tid & 63, sl = tid >> 6;
        int idx;
        if (s_is64) idx = (int)((const long long*)seq)[b * SS + s0 + sl];
        else        idx = ((const int*)seq)[b * SS + s0 + sl];
        rows[tid] = idx;
    }
    __syncthreads();

    const int tx = tid & 15;
    const int ty = tid >> 4;
    const int arow = tid >> 1;
    const int ak   = (tid & 1) * 8;
    const int wrow = tid >> 2;
    const int wk   = (tid & 3) * 4;

    const float* aptr = emb + (size_t)rows[arow] * EE + ak;
    const float* wptr = Wih + (size_t)(g0 + wrow) * EE + wk;

    u64 cc[4][4];
    #pragma unroll
    for (int p = 0; p < 4; p++)
        #pragma unroll
        for (int jn = 0; jn < 4; jn++) cc[p][jn] = 0ull;

    // prefetch tile 0
    float4 ra0 = *(const float4*)aptr;
    float4 ra1 = *(const float4*)(aptr + 4);
    float4 rw  = *(const float4*)wptr;

    for (int k0 = 0; k0 < EE; k0 += 16) {
        // commit staged regs to smem
        As[ak + 0][arow] = ra0.x; As[ak + 1][arow] = ra0.y;
        As[ak + 2][arow] = ra0.z; As[ak + 3][arow] = ra0.w;
        As[ak + 4][arow] = ra1.x; As[ak + 5][arow] = ra1.y;
        As[ak + 6][arow] = ra1.z; As[ak + 7][arow] = ra1.w;
        Bs2[wk + 0][wrow] = make_float2(rw.x, rw.x);
        Bs2[wk + 1][wrow] = make_float2(rw.y, rw.y);
        Bs2[wk + 2][wrow] = make_float2(rw.z, rw.z);
        Bs2[wk + 3][wrow] = make_float2(rw.w, rw.w);
        __syncthreads();

        // issue next tile's loads (latency overlaps compute below)
        if (k0 + 16 < EE) {
            ra0 = *(const float4*)(aptr + k0 + 16);
            ra1 = *(const float4*)(aptr + k0 + 20);
            rw  = *(const float4*)(wptr + k0 + 16);
        }

        #pragma unroll
        for (int kk = 0; kk < 16; kk++) {
            u64 a0p = *(const u64*)&As[kk][0 * 32 + tx * 2];
            u64 a1p = *(const u64*)&As[kk][1 * 32 + tx * 2];
            u64 a2p = *(const u64*)&As[kk][2 * 32 + tx * 2];
            u64 a3p = *(const u64*)&As[kk][3 * 32 + tx * 2];
            u64 w0 = *(const u64*)&Bs2[kk][ty * 4 + 0];
            u64 w1 = *(const u64*)&Bs2[kk][ty * 4 + 1];
            u64 w2 = *(const u64*)&Bs2[kk][ty * 4 + 2];
            u64 w3 = *(const u64*)&Bs2[kk][ty * 4 + 3];
            cc[0][0] = fma2(a0p, w0, cc[0][0]); cc[1][0] = fma2(a1p, w0, cc[1][0]);
            cc[2][0] = fma2(a2p, w0, cc[2][0]); cc[3][0] = fma2(a3p, w0, cc[3][0]);
            cc[0][1] = fma2(a0p, w1, cc[0][1]); cc[1][1] = fma2(a1p, w1, cc[1][1]);
            cc[2][1] = fma2(a2p, w1, cc[2][1]); cc[3][1] = fma2(a3p, w1, cc[3][1]);
            cc[0][2] = fma2(a0p, w2, cc[0][2]); cc[1][2] = fma2(a1p, w2, cc[1][2]);
            cc[2][2] = fma2(a2p, w2, cc[2][2]); cc[3][2] = fma2(a3p, w2, cc[3][2]);
            cc[0][3] = fma2(a0p, w3, cc[0][3]); cc[1][3] = fma2(a1p, w3, cc[1][3]);
            cc[2][3] = fma2(a2p, w3, cc[2][3]); cc[3][3] = fma2(a3p, w3, cc[3][3]);
        }
        __syncthreads();
    }

    #pragma unroll
    for (int jn = 0; jn < 4; jn++) {
        int g = g0 + ty * 4 + jn;
        float bsum = bih[g] + bhh[g];
        #pragma unroll
        for (int p = 0; p < 4; p++) {
            float2 v = unpack2(cc[p][jn]);
            int s = s0 + (p >> 1);
            int b = (p & 1) * 32 + tx * 2;
            __stcs((float2*)&g_xg[(size_t)s * (GG * BB) + (size_t)g * BB + b],
                   make_float2(v.x + bsum, v.y + bsum));
        }
    }
}

// ---------------------------------------------------------------------------
// Phase B: persistent LSTM recurrence, dataflow-synced (NO grid barrier).
// R6 structure: 128 CTAs x 256 threads; warp wi owns k-range [wi*64,+64) x
// all 64 b; ONE acquire-poll per warp per step over its 16 producer flags.
// Flag bump via st.release (own flag, no RMW). xg read with ld.cs
// (streaming) so the 256MB xg stream does not evict the L2-resident h ring.
// ---------------------------------------------------------------------------
__global__ void __launch_bounds__(256, 1) lstm_kernel(
    const float* __restrict__ Whh, float* __restrict__ out, int write_c)
{
    extern __shared__ float smf[];
    float*  Ws  = smf;                      // (st*512+k)*2 : {w_jA, w_jB}
    float2* scp = (float2*)(smf + 8192);    // [st8][bh2][kr8][lane32]
    __shared__ u32 s_base;

    const int tid  = threadIdx.x;
    const int wi   = tid >> 5;
    const int lane = tid & 31;
    const int cta  = blockIdx.x;
    const int j0   = cta * 4;
    const int kbase = wi * 64;

    if (tid == 0) s_base = g_wf[cta];

    #pragma unroll
    for (int st = 0; st < 8; st++) {
        int g = st >> 1, jp = st & 1;
        const float* r0 = Whh + (size_t)(g * HH + j0 + 2 * jp) * HH;
        const float* r1 = r0 + HH;
        #pragma unroll
        for (int i = 0; i < 2; i++) {
            int k = tid + i * 256;
            *(float2*)&Ws[(st * 512 + k) * 2] = make_float2(r0[k], r1[k]);
        }
    }
    __syncthreads();

    const int b  = tid & 63;
    const int jj = tid >> 6;
    const int j  = j0 + jj;
    const int jp_r  = jj >> 1;
    const int comp  = jj & 1;
    const int bh_r  = b >> 5;
    const int lane_r = b & 31;
    const u32 base = s_base;

    float c_reg = 0.f, h_val = 0.f;

    #pragma unroll 1
    for (int s = 0; s < SS; s++) {
        // xg precomputed: streaming loads, overlapped with the whole GEMM
        float xgv[4];
        const float* xgs = g_xg + (size_t)s * (GG * BB);
        #pragma unroll
        for (int g = 0; g < 4; g++)
            xgv[g] = __ldcs(&xgs[(g * HH + j) * BB + b]);

        u64 acc[8][2];
        #pragma unroll
        for (int st = 0; st < 8; st++) { acc[st][0] = 0ull; acc[st][1] = 0ull; }

        if (s > 0) {
            // single wait: the 16 producer CTAs of OUR k-range
            const u32 target = base + (u32)s;
            int ok, first = 1;
            do {
                if (!first) __nanosleep(20);
                first = 0;
                ok = 1;
                if (lane < 16) {
                    u32 f;
                    asm volatile("ld.acquire.gpu.global.u32 %0, [%1];"
                                 : "=r"(f) : "l"(&g_wf[wi * 16 + lane]));
                    ok = ((int)(f - target) >= 0);
                }
            } while (__all_sync(0xffffffffu, ok) == 0);

            const float* hsrc = g_h[(s - 1) & 3];
            float hreg[2][32];
            #pragma unroll
            for (int i = 0; i < 16; i++) {
                hreg[0][i]      = __ldcg(&hsrc[(kbase + i) * 64 + lane]);
                hreg[0][16 + i] = __ldcg(&hsrc[(kbase + i) * 64 + 32 + lane]);
            }
            #pragma unroll
            for (int c = 0; c < 4; c++) {
                const int cur = c & 1, nxt = cur ^ 1;
                if (c < 3) {
                    const int kn = kbase + (c + 1) * 16;
                    #pragma unroll
                    for (int i = 0; i < 16; i++) {
                        hreg[nxt][i]      = __ldcg(&hsrc[(kn + i) * 64 + lane]);
                        hreg[nxt][16 + i] = __ldcg(&hsrc[(kn + i) * 64 + 32 + lane]);
                    }
                }
                const int kg0 = kbase + c * 16;
                #pragma unroll
                for (int kk = 0; kk < 16; kk += 2) {
                    const int kg = kg0 + kk;
                    u64 dA0 = pack2(hreg[cur][kk],          hreg[cur][kk]);
                    u64 dB0 = pack2(hreg[cur][16 + kk],     hreg[cur][16 + kk]);
                    u64 dA1 = pack2(hreg[cur][kk + 1],      hreg[cur][kk + 1]);
                    u64 dB1 = pack2(hreg[cur][16 + kk + 1], hreg[cur][16 + kk + 1]);
                    #pragma unroll
                    for (int st = 0; st < 8; st++) {
                        ulonglong2 wv = *(const ulonglong2*)&Ws[(st * 512 + kg) * 2];
                        acc[st][0] = fma2(dA0, wv.x, acc[st][0]);
                        acc[st][1] = fma2(dB0, wv.x, acc[st][1]);
                        acc[st][0] = fma2(dA1, wv.y, acc[st][0]);
                        acc[st][1] = fma2(dB1, wv.y, acc[st][1]);
                    }
                }
            }
        }

        // partials -> scratch [st][bh][kr][lane]
        #pragma unroll
        for (int st = 0; st < 8; st++) {
            scp[((st * 2 + 0) * 8 + wi) * 32 + lane] = *(float2*)&acc[st][0];
            scp[((st * 2 + 1) * 8 + wi) * 32 + lane] = *(float2*)&acc[st][1];
        }
        __syncthreads();

        // cross-warp reduce in packed f32x2 + gates
        float gt[4];
        #pragma unroll
        for (int g = 0; g < 4; g++) {
            int st = g * 2 + jp_r;
            const u64* rb = (const u64*)&scp[((st * 2 + bh_r) * 8) * 32 + lane_r];
            u64 v0 = add2(rb[0 * 32], rb[1 * 32]);
            u64 v1 = add2(rb[2 * 32], rb[3 * 32]);
            u64 v2 = add2(rb[4 * 32], rb[5 * 32]);
            u64 v3 = add2(rb[6 * 32], rb[7 * 32]);
            float2 r = unpack2(add2(add2(v0, v1), add2(v2, v3)));
            gt[g] = (comp ? r.y : r.x) + xgv[g];
        }
        float ig = sigf(gt[0]), fg = sigf(gt[1]);
        float gg = tanh_f(gt[2]), og = sigf(gt[3]);
        c_reg = fg * c_reg + ig * gg;
        h_val = og * tanh_f(c_reg);

        __stcg(&g_h[s & 3][j * 64 + b], h_val);
        __syncthreads();   // all h stores of this CTA issued before flag bump
        if (tid == 0) {
            asm volatile("st.release.gpu.global.u32 [%0], %1;"
                         :: "l"(&g_wf[cta]), "r"(base + (u32)s + 1u) : "memory");
        }
    }

    out[b * HH + j] = h_val;
    if (write_c) out[BB * HH + b * HH + j] = c_reg;
}

// ---------------------------------------------------------------------------
// kernel_launch
// ---------------------------------------------------------------------------
extern "C" void kernel_launch(void* const* d_in, const int* in_sizes, int n_in,
                              void* d_out, int out_size)
{
    const void*  seq = d_in[0];
    const float* emb = (const float*)d_in[1];
    const float* Wih = (const float*)d_in[2];
    const float* Whh = (const float*)d_in[3];
    const float* bih = (const float*)d_in[4];
    const float* bhh = (const float*)d_in[5];
    float* out = (float*)d_out;

    (void)in_sizes; (void)n_in;
    int write_c = (out_size >= 2 * BB * HH) ? 1 : 0;

    static const int kSmem = (8192 + 8192) * (int)sizeof(float);
    cudaFuncSetAttribute(lstm_kernel, cudaFuncAttributeMaxDynamicSharedMemorySize, kSmem);

    xgates_gemm<<<dim3(GG / 64, SS / 2), 256>>>(seq, emb, Wih, bih, bhh);
    lstm_kernel<<<HH / 4, 256, kSmem>>>(Whh, out, write_c);
}

// round 9
// speedup vs baseline: 1.3036x; 1.3036x over previous
#include <cuda_runtime.h>

#define BB 64      // batch
#define SS 512     // sequence length
#define EE 256     // embedding dim
#define HH 512     // hidden
#define GG 2048    // 4*H gate rows

typedef unsigned long long u64;
typedef unsigned int u32;

// ---------------------------------------------------------------------------
// Device globals
// ---------------------------------------------------------------------------
__device__ u32 g_wf[256];                     // per-CTA h write-flags (monotonic)
__device__ float g_xg[SS * GG * BB];          // x_gates [s][g][b]
__device__ float g_h[4][HH * BB];             // h ring: slot s&3 = h(s), [k][b]

// ---------------------------------------------------------------------------
// f32x2 helpers (packed FFMA2/FADD2 -- only reachable via PTX)
// ---------------------------------------------------------------------------
__device__ __forceinline__ u64 fma2(u64 a, u64 b, u64 c) {
    u64 d; asm("fma.rn.f32x2 %0, %1, %2, %3;" : "=l"(d) : "l"(a), "l"(b), "l"(c)); return d;
}
__device__ __forceinline__ u64 add2(u64 a, u64 b) {
    u64 d; asm("add.rn.f32x2 %0, %1, %2;" : "=l"(d) : "l"(a), "l"(b)); return d;
}
__device__ __forceinline__ u64 pack2(float x, float y) {
    u64 d; asm("mov.b64 %0, {%1, %2};" : "=l"(d) : "f"(x), "f"(y)); return d;
}
__device__ __forceinline__ float2 unpack2(u64 v) {
    float2 r; asm("mov.b64 {%0, %1}, %2;" : "=f"(r.x), "=f"(r.y) : "l"(v)); return r;
}
__device__ __forceinline__ float sigf(float x) { return 1.f / (1.f + __expf(-x)); }
__device__ __forceinline__ float tanh_f(float x) { return 2.f / (1.f + __expf(-2.f * x)) - 1.f; }

// ---------------------------------------------------------------------------
// Phase A: x_gates[s][g][b] = emb[seq[b][s]] . W_ih[g] + b_ih[g] + b_hh[g]
// 128x64 tile, BK=16, 8Mx4N f32x2 micro, register-staged double buffering.
// Plain (default-policy) stores: the lstm consumes xg from L2 in write order.
// ---------------------------------------------------------------------------
__global__ void __launch_bounds__(256) xgates_gemm(
    const void* __restrict__ seq,
    const float* __restrict__ emb,
    const float* __restrict__ Wih,
    const float* __restrict__ bih,
    const float* __restrict__ bhh)
{
    __shared__ float  As[16][132];
    __shared__ float2 Bs2[16][66];
    __shared__ int rows[128];
    __shared__ int s_is64;

    const int tid = threadIdx.x;
    const int s0 = blockIdx.y * 2;
    const int g0 = blockIdx.x * 64;

    if (tid == 0) s_is64 = 1;
    __syncthreads();
    if (tid < 64) {
        if (((const u32*)seq)[2 * tid + 1] != 0u) s_is64 = 0;
    }
    __syncthreads();
    if (tid < 128) {
        int b = tid & 63, sl = tid >> 6;
        int idx;
        if (s_is64) idx = (int)((const long long*)seq)[b * SS + s0 + sl];
        else        idx = ((const int*)seq)[b * SS + s0 + sl];
        rows[tid] = idx;
    }
    __syncthreads();

    const int tx = tid & 15;
    const int ty = tid >> 4;
    const int arow = tid >> 1;
    const int ak   = (tid & 1) * 8;
    const int wrow = tid >> 2;
    const int wk   = (tid & 3) * 4;

    const float* aptr = emb + (size_t)rows[arow] * EE + ak;
    const float* wptr = Wih + (size_t)(g0 + wrow) * EE + wk;

    u64 cc[4][4];
    #pragma unroll
    for (int p = 0; p < 4; p++)
        #pragma unroll
        for (int jn = 0; jn < 4; jn++) cc[p][jn] = 0ull;

    float4 ra0 = *(const float4*)aptr;
    float4 ra1 = *(const float4*)(aptr + 4);
    float4 rw  = *(const float4*)wptr;

    for (int k0 = 0; k0 < EE; k0 += 16) {
        As[ak + 0][arow] = ra0.x; As[ak + 1][arow] = ra0.y;
        As[ak + 2][arow] = ra0.z; As[ak + 3][arow] = ra0.w;
        As[ak + 4][arow] = ra1.x; As[ak + 5][arow] = ra1.y;
        As[ak + 6][arow] = ra1.z; As[ak + 7][arow] = ra1.w;
        Bs2[wk + 0][wrow] = make_float2(rw.x, rw.x);
        Bs2[wk + 1][wrow] = make_float2(rw.y, rw.y);
        Bs2[wk + 2][wrow] = make_float2(rw.z, rw.z);
        Bs2[wk + 3][wrow] = make_float2(rw.w, rw.w);
        __syncthreads();

        if (k0 + 16 < EE) {   // next tile's loads overlap compute
            ra0 = *(const float4*)(aptr + k0 + 16);
            ra1 = *(const float4*)(aptr + k0 + 20);
            rw  = *(const float4*)(wptr + k0 + 16);
        }

        #pragma unroll
        for (int kk = 0; kk < 16; kk++) {
            u64 a0p = *(const u64*)&As[kk][0 * 32 + tx * 2];
            u64 a1p = *(const u64*)&As[kk][1 * 32 + tx * 2];
            u64 a2p = *(const u64*)&As[kk][2 * 32 + tx * 2];
            u64 a3p = *(const u64*)&As[kk][3 * 32 + tx * 2];
            u64 w0 = *(const u64*)&Bs2[kk][ty * 4 + 0];
            u64 w1 = *(const u64*)&Bs2[kk][ty * 4 + 1];
            u64 w2 = *(const u64*)&Bs2[kk][ty * 4 + 2];
            u64 w3 = *(const u64*)&Bs2[kk][ty * 4 + 3];
            cc[0][0] = fma2(a0p, w0, cc[0][0]); cc[1][0] = fma2(a1p, w0, cc[1][0]);
            cc[2][0] = fma2(a2p, w0, cc[2][0]); cc[3][0] = fma2(a3p, w0, cc[3][0]);
            cc[0][1] = fma2(a0p, w1, cc[0][1]); cc[1][1] = fma2(a1p, w1, cc[1][1]);
            cc[2][1] = fma2(a2p, w1, cc[2][1]); cc[3][1] = fma2(a3p, w1, cc[3][1]);
            cc[0][2] = fma2(a0p, w2, cc[0][2]); cc[1][2] = fma2(a1p, w2, cc[1][2]);
            cc[2][2] = fma2(a2p, w2, cc[2][2]); cc[3][2] = fma2(a3p, w2, cc[3][2]);
            cc[0][3] = fma2(a0p, w3, cc[0][3]); cc[1][3] = fma2(a1p, w3, cc[1][3]);
            cc[2][3] = fma2(a2p, w3, cc[2][3]); cc[3][3] = fma2(a3p, w3, cc[3][3]);
        }
        __syncthreads();
    }

    #pragma unroll
    for (int jn = 0; jn < 4; jn++) {
        int g = g0 + ty * 4 + jn;
        float bsum = bih[g] + bhh[g];
        #pragma unroll
        for (int p = 0; p < 4; p++) {
            float2 v = unpack2(cc[p][jn]);
            int s = s0 + (p >> 1);
            int b = (p & 1) * 32 + tx * 2;
            *(float2*)&g_xg[(size_t)s * (GG * BB) + (size_t)g * BB + b] =
                make_float2(v.x + bsum, v.y + bsum);
        }
    }
}

// ---------------------------------------------------------------------------
// Phase B: persistent LSTM recurrence, dataflow-synced, 2 CTAs/SM.
// 256 CTAs x 256 threads. CTA owns 2 h-columns j0=cta*2 (4 f32x2 streams).
// Warp wi owns k-range [wi*64,+64) x all 64 b; ONE acquire-poll per warp
// per step over its 32 producer flags (one lane each). h prefetched in
// 8-k chunks (double-buffered regs) to keep regs <= 128 for occupancy 2:
// the co-resident CTA absorbs the sync/latency stalls.
// SMEM: W pairs 16KB | scratch 16KB = 32KB.
// ---------------------------------------------------------------------------
__global__ void __launch_bounds__(256, 2) lstm_kernel(
    const float* __restrict__ Whh, float* __restrict__ out, int write_c)
{
    extern __shared__ float smf[];
    float*  Ws  = smf;                      // (st*512+k)*2 : {w_j0, w_j1}, st=gate
    float2* scp = (float2*)(smf + 4096);    // [st4][bh2][kr8][lane32]
    __shared__ u32 s_base;

    const int tid  = threadIdx.x;
    const int wi   = tid >> 5;
    const int lane = tid & 31;
    const int cta  = blockIdx.x;
    const int j0   = cta * 2;
    const int kbase = wi * 64;

    if (tid == 0) s_base = g_wf[cta];

    // W pairs: stream st = gate g covers rows (g*H + j0, g*H + j0 + 1)
    #pragma unroll
    for (int st = 0; st < 4; st++) {
        const float* r0 = Whh + (size_t)(st * HH + j0) * HH;
        const float* r1 = r0 + HH;
        #pragma unroll
        for (int i = 0; i < 2; i++) {
            int k = tid + i * 256;
            *(float2*)&Ws[(st * 512 + k) * 2] = make_float2(r0[k], r1[k]);
        }
    }
    __syncthreads();

    const int b  = tid & 63;        // epilogue (tid < 128): one (b, j) per thread
    const int jj = tid >> 6;        // 0..3; only 0,1 do epilogue
    const int j  = j0 + jj;
    const int bh_r  = b >> 5;
    const int lane_r = b & 31;
    const u32 base = s_base;

    float c_reg = 0.f, h_val = 0.f;

    #pragma unroll 1
    for (int s = 0; s < SS; s++) {
        // xg precomputed: default-policy loads (L2-resident from GEMM)
        float xgv[4];
        if (jj < 2) {
            const float* xgs = g_xg + (size_t)s * (GG * BB);
            #pragma unroll
            for (int g = 0; g < 4; g++)
                xgv[g] = __ldg(&xgs[(g * HH + j) * BB + b]);
        }

        u64 acc[4][2];
        #pragma unroll
        for (int st = 0; st < 4; st++) { acc[st][0] = 0ull; acc[st][1] = 0ull; }

        if (s > 0) {
            // single wait: the 32 producer CTAs of OUR k-range (1 flag/lane)
            const u32 target = base + (u32)s;
            int ok, first = 1;
            do {
                if (!first) __nanosleep(20);
                first = 0;
                u32 f;
                asm volatile("ld.acquire.gpu.global.u32 %0, [%1];"
                             : "=r"(f) : "l"(&g_wf[wi * 32 + lane]));
                ok = ((int)(f - target) >= 0);
            } while (__all_sync(0xffffffffu, ok) == 0);

            const float* hsrc = g_h[(s - 1) & 3];
            float hreg[2][16];
            // prefetch chunk 0 (8 k x {lane, lane+32})
            #pragma unroll
            for (int i = 0; i < 8; i++) {
                hreg[0][i]     = __ldcg(&hsrc[(kbase + i) * 64 + lane]);
                hreg[0][8 + i] = __ldcg(&hsrc[(kbase + i) * 64 + 32 + lane]);
            }
            #pragma unroll
            for (int c = 0; c < 8; c++) {
                const int cur = c & 1, nxt = cur ^ 1;
                if (c < 7) {
                    const int kn = kbase + (c + 1) * 8;
                    #pragma unroll
                    for (int i = 0; i < 8; i++) {
                        hreg[nxt][i]     = __ldcg(&hsrc[(kn + i) * 64 + lane]);
                        hreg[nxt][8 + i] = __ldcg(&hsrc[(kn + i) * 64 + 32 + lane]);
                    }
                }
                const int kg0 = kbase + c * 8;
                #pragma unroll
                for (int kk = 0; kk < 8; kk += 2) {
                    const int kg = kg0 + kk;
                    u64 dA0 = pack2(hreg[cur][kk],         hreg[cur][kk]);
                    u64 dB0 = pack2(hreg[cur][8 + kk],     hreg[cur][8 + kk]);
                    u64 dA1 = pack2(hreg[cur][kk + 1],     hreg[cur][kk + 1]);
                    u64 dB1 = pack2(hreg[cur][8 + kk + 1], hreg[cur][8 + kk + 1]);
                    #pragma unroll
                    for (int st = 0; st < 4; st++) {
                        ulonglong2 wv = *(const ulonglong2*)&Ws[(st * 512 + kg) * 2];
                        acc[st][0] = fma2(dA0, wv.x, acc[st][0]);
                        acc[st][1] = fma2(dB0, wv.x, acc[st][1]);
                        acc[st][0] = fma2(dA1, wv.y, acc[st][0]);
                        acc[st][1] = fma2(dB1, wv.y, acc[st][1]);
                    }
                }
            }
        }

        // partials -> scratch [st][bh][kr][lane]
        #pragma unroll
        for (int st = 0; st < 4; st++) {
            scp[((st * 2 + 0) * 8 + wi) * 32 + lane] = *(float2*)&acc[st][0];
            scp[((st * 2 + 1) * 8 + wi) * 32 + lane] = *(float2*)&acc[st][1];
        }
        __syncthreads();

        if (jj < 2) {
            float gt[4];
            #pragma unroll
            for (int g = 0; g < 4; g++) {
                const u64* rb = (const u64*)&scp[((g * 2 + bh_r) * 8) * 32 + lane_r];
                u64 v0 = add2(rb[0 * 32], rb[1 * 32]);
                u64 v1 = add2(rb[2 * 32], rb[3 * 32]);
                u64 v2 = add2(rb[4 * 32], rb[5 * 32]);
                u64 v3 = add2(rb[6 * 32], rb[7 * 32]);
                float2 r = unpack2(add2(add2(v0, v1), add2(v2, v3)));
                gt[g] = (jj ? r.y : r.x) + xgv[g];
            }
            float ig = sigf(gt[0]), fg = sigf(gt[1]);
            float gg = tanh_f(gt[2]), og = sigf(gt[3]);
            c_reg = fg * c_reg + ig * gg;
            h_val = og * tanh_f(c_reg);
            __stcg(&g_h[s & 3][j * 64 + b], h_val);
        }
        __syncthreads();   // all h stores of this CTA issued before flag bump
        if (tid == 0) {
            asm volatile("red.release.gpu.global.add.u32 [%0], %1;"
                         :: "l"(&g_wf[cta]), "r"(1u) : "memory");
        }
    }

    if (jj < 2) {
        out[b * HH + j] = h_val;
        if (write_c) out[BB * HH + b * HH + j] = c_reg;
    }
}

// ---------------------------------------------------------------------------
// kernel_launch
// ---------------------------------------------------------------------------
extern "C" void kernel_launch(void* const* d_in, const int* in_sizes, int n_in,
                              void* d_out, int out_size)
{
    const void*  seq = d_in[0];
    const float* emb = (const float*)d_in[1];
    const float* Wih = (const float*)d_in[2];
    const float* Whh = (const float*)d_in[3];
    const float* bih = (const float*)d_in[4];
    const float* bhh = (const float*)d_in[5];
    float* out = (float*)d_out;

    (void)in_sizes; (void)n_in;
    int write_c = (out_size >= 2 * BB * HH) ? 1 : 0;

    // 32 KB dynamic SMEM per CTA: W pairs 16K + scratch 16K (2 CTAs/SM)
    static const int kSmem = (4096 + 4096) * (int)sizeof(float);
    cudaFuncSetAttribute(lstm_kernel, cudaFuncAttributeMaxDynamicSharedMemorySize, kSmem);

    xgates_gemm<<<dim3(GG / 64, SS / 2), 256>>>(seq, emb, Wih, bih, bhh);
    lstm_kernel<<<HH / 2, 256, kSmem>>>(Whh, out, write_c);
}

// round 10
// speedup vs baseline: 1.4683x; 1.1263x over previous
#include <cuda_runtime.h>

#define BB 64      // batch
#define SS 512     // sequence length
#define EE 256     // embedding dim
#define HH 512     // hidden
#define GG 2048    // 4*H gate rows

typedef unsigned long long u64;
typedef unsigned int u32;

// ---------------------------------------------------------------------------
// Device globals
// ---------------------------------------------------------------------------
__device__ u32 g_wf[128];                     // per-CTA h write-flags (monotonic)
__device__ float g_xg[SS * GG * BB];          // x_gates [s][g][b]
__device__ float g_h[4][HH * BB];             // h ring: slot s&3 = h(s), [k][b]

// ---------------------------------------------------------------------------
// f32x2 helpers (packed FFMA2/FADD2 -- only reachable via PTX)
// ---------------------------------------------------------------------------
__device__ __forceinline__ u64 fma2(u64 a, u64 b, u64 c) {
    u64 d; asm("fma.rn.f32x2 %0, %1, %2, %3;" : "=l"(d) : "l"(a), "l"(b), "l"(c)); return d;
}
__device__ __forceinline__ u64 add2(u64 a, u64 b) {
    u64 d; asm("add.rn.f32x2 %0, %1, %2;" : "=l"(d) : "l"(a), "l"(b)); return d;
}
__device__ __forceinline__ u64 pack2(float x, float y) {
    u64 d; asm("mov.b64 %0, {%1, %2};" : "=l"(d) : "f"(x), "f"(y)); return d;
}
__device__ __forceinline__ float2 unpack2(u64 v) {
    float2 r; asm("mov.b64 {%0, %1}, %2;" : "=f"(r.x), "=f"(r.y) : "l"(v)); return r;
}
__device__ __forceinline__ float sigf(float x) { return 1.f / (1.f + __expf(-x)); }
__device__ __forceinline__ float tanh_f(float x) { return 2.f / (1.f + __expf(-2.f * x)) - 1.f; }

// ---------------------------------------------------------------------------
// Phase A: x_gates[s][g][b] = emb[seq[b][s]] . W_ih[g] + b_ih[g] + b_hh[g]
// 128x64 tile, BK=16, 8Mx4N f32x2 micro, register-staged double buffering.
// ---------------------------------------------------------------------------
__global__ void __launch_bounds__(256) xgates_gemm(
    const void* __restrict__ seq,
    const float* __restrict__ emb,
    const float* __restrict__ Wih,
    const float* __restrict__ bih,
    const float* __restrict__ bhh)
{
    __shared__ float  As[16][132];
    __shared__ float2 Bs2[16][66];
    __shared__ int rows[128];
    __shared__ int s_is64;

    const int tid = threadIdx.x;
    const int s0 = blockIdx.y * 2;
    const int g0 = blockIdx.x * 64;

    if (tid == 0) s_is64 = 1;
    __syncthreads();
    if (tid < 64) {
        if (((const u32*)seq)[2 * tid + 1] != 0u) s_is64 = 0;
    }
    __syncthreads();
    if (tid < 128) {
        int b = tid & 63, sl = tid >> 6;
        int idx;
        if (s_is64) idx = (int)((const long long*)seq)[b * SS + s0 + sl];
        else        idx = ((const int*)seq)[b * SS + s0 + sl];
        rows[tid] = idx;
    }
    __syncthreads();

    const int tx = tid & 15;
    const int ty = tid >> 4;
    const int arow = tid >> 1;
    const int ak   = (tid & 1) * 8;
    const int wrow = tid >> 2;
    const int wk   = (tid & 3) * 4;

    const float* aptr = emb + (size_t)rows[arow] * EE + ak;
    const float* wptr = Wih + (size_t)(g0 + wrow) * EE + wk;

    u64 cc[4][4];
    #pragma unroll
    for (int p = 0; p < 4; p++)
        #pragma unroll
        for (int jn = 0; jn < 4; jn++) cc[p][jn] = 0ull;

    float4 ra0 = *(const float4*)aptr;
    float4 ra1 = *(const float4*)(aptr + 4);
    float4 rw  = *(const float4*)wptr;

    for (int k0 = 0; k0 < EE; k0 += 16) {
        As[ak + 0][arow] = ra0.x; As[ak + 1][arow] = ra0.y;
        As[ak + 2][arow] = ra0.z; As[ak + 3][arow] = ra0.w;
        As[ak + 4][arow] = ra1.x; As[ak + 5][arow] = ra1.y;
        As[ak + 6][arow] = ra1.z; As[ak + 7][arow] = ra1.w;
        Bs2[wk + 0][wrow] = make_float2(rw.x, rw.x);
        Bs2[wk + 1][wrow] = make_float2(rw.y, rw.y);
        Bs2[wk + 2][wrow] = make_float2(rw.z, rw.z);
        Bs2[wk + 3][wrow] = make_float2(rw.w, rw.w);
        __syncthreads();

        if (k0 + 16 < EE) {   // next tile's loads overlap compute
            ra0 = *(const float4*)(aptr + k0 + 16);
            ra1 = *(const float4*)(aptr + k0 + 20);
            rw  = *(const float4*)(wptr + k0 + 16);
        }

        #pragma unroll
        for (int kk = 0; kk < 16; kk++) {
            u64 a0p = *(const u64*)&As[kk][0 * 32 + tx * 2];
            u64 a1p = *(const u64*)&As[kk][1 * 32 + tx * 2];
            u64 a2p = *(const u64*)&As[kk][2 * 32 + tx * 2];
            u64 a3p = *(const u64*)&As[kk][3 * 32 + tx * 2];
            u64 w0 = *(const u64*)&Bs2[kk][ty * 4 + 0];
            u64 w1 = *(const u64*)&Bs2[kk][ty * 4 + 1];
            u64 w2 = *(const u64*)&Bs2[kk][ty * 4 + 2];
            u64 w3 = *(const u64*)&Bs2[kk][ty * 4 + 3];
            cc[0][0] = fma2(a0p, w0, cc[0][0]); cc[1][0] = fma2(a1p, w0, cc[1][0]);
            cc[2][0] = fma2(a2p, w0, cc[2][0]); cc[3][0] = fma2(a3p, w0, cc[3][0]);
            cc[0][1] = fma2(a0p, w1, cc[0][1]); cc[1][1] = fma2(a1p, w1, cc[1][1]);
            cc[2][1] = fma2(a2p, w1, cc[2][1]); cc[3][1] = fma2(a3p, w1, cc[3][1]);
            cc[0][2] = fma2(a0p, w2, cc[0][2]); cc[1][2] = fma2(a1p, w2, cc[1][2]);
            cc[2][2] = fma2(a2p, w2, cc[2][2]); cc[3][2] = fma2(a3p, w2, cc[3][2]);
            cc[0][3] = fma2(a0p, w3, cc[0][3]); cc[1][3] = fma2(a1p, w3, cc[1][3]);
            cc[2][3] = fma2(a2p, w3, cc[2][3]); cc[3][3] = fma2(a3p, w3, cc[3][3]);
        }
        __syncthreads();
    }

    #pragma unroll
    for (int jn = 0; jn < 4; jn++) {
        int g = g0 + ty * 4 + jn;
        float bsum = bih[g] + bhh[g];
        #pragma unroll
        for (int p = 0; p < 4; p++) {
            float2 v = unpack2(cc[p][jn]);
            int s = s0 + (p >> 1);
            int b = (p & 1) * 32 + tx * 2;
            *(float2*)&g_xg[(size_t)s * (GG * BB) + (size_t)g * BB + b] =
                make_float2(v.x + bsum, v.y + bsum);
        }
    }
}

// ---------------------------------------------------------------------------
// Phase B: persistent LSTM recurrence, dataflow-synced (NO grid barrier).
// 128 CTAs x 256 threads (8 warps). CTA owns 4 h-columns (8 f32x2 streams,
// vector = j-pair). Warp wi owns k-range [wi*64,+64); lane owns b-pair
// (2*lane, 2*lane+1) -> h loads are LDG.64 (half the LSU issue of LDG.32).
// h pipelined in 8-k chunks, prefetch distance 3 (4 reg buffers) to cover
// loaded-L2 latency. ONE acquire-poll per warp per step (16 producer flags).
// SMEM: W pairs 32KB | scratch 32KB = 64KB.
// ---------------------------------------------------------------------------
__global__ void __launch_bounds__(256, 1) lstm_kernel(
    const float* __restrict__ Whh, float* __restrict__ out, int write_c)
{
    extern __shared__ float smf[];
    float*  Ws  = smf;                      // (st*512+k)*2 : {w_jA, w_jB}
    float2* scp = (float2*)(smf + 8192);    // [st8][kr8][b64] float2
    __shared__ u32 s_base;

    const int tid  = threadIdx.x;
    const int wi   = tid >> 5;
    const int lane = tid & 31;
    const int cta  = blockIdx.x;
    const int j0   = cta * 4;
    const int kbase = wi * 64;

    if (tid == 0) s_base = g_wf[cta];

    // W pairs: st = g*2+jp covers rows (g*H + j0+2jp, +1)
    #pragma unroll
    for (int st = 0; st < 8; st++) {
        int g = st >> 1, jp = st & 1;
        const float* r0 = Whh + (size_t)(g * HH + j0 + 2 * jp) * HH;
        const float* r1 = r0 + HH;
        #pragma unroll
        for (int i = 0; i < 2; i++) {
            int k = tid + i * 256;
            *(float2*)&Ws[(st * 512 + k) * 2] = make_float2(r0[k], r1[k]);
        }
    }
    __syncthreads();

    const int b  = tid & 63;        // epilogue: one (b, j) per thread
    const int jj = tid >> 6;
    const int j  = j0 + jj;
    const int jp_r = jj >> 1;
    const int comp = jj & 1;
    const u32 base = s_base;

    float c_reg = 0.f, h_val = 0.f;

    #pragma unroll 1
    for (int s = 0; s < SS; s++) {
        // xg precomputed: L2-resident from GEMM, loads overlap the wait
        float xgv[4];
        const float* xgs = g_xg + (size_t)s * (GG * BB);
        #pragma unroll
        for (int g = 0; g < 4; g++)
            xgv[g] = __ldg(&xgs[(g * HH + j) * BB + b]);

        u64 acc[8][2];
        #pragma unroll
        for (int st = 0; st < 8; st++) { acc[st][0] = 0ull; acc[st][1] = 0ull; }

        if (s > 0) {
            // single wait: the 16 producer CTAs of OUR k-range
            const u32 target = base + (u32)s;
            int ok, first = 1;
            do {
                if (!first) __nanosleep(20);
                first = 0;
                ok = 1;
                if (lane < 16) {
                    u32 f;
                    asm volatile("ld.acquire.gpu.global.u32 %0, [%1];"
                                 : "=r"(f) : "l"(&g_wf[wi * 16 + lane]));
                    ok = ((int)(f - target) >= 0);
                }
            } while (__all_sync(0xffffffffu, ok) == 0);

            const float2* hsrc = (const float2*)g_h[(s - 1) & 3];  // [k][b/2]
            float2 hreg[4][8];   // 4 buffers x 8 k (b-pair per lane)

            // prefetch chunks 0,1,2 back-to-back (24 LDG.64 in flight)
            #pragma unroll
            for (int c = 0; c < 3; c++)
                #pragma unroll
                for (int i = 0; i < 8; i++)
                    hreg[c][i] = __ldcg(&hsrc[(kbase + c * 8 + i) * 32 + lane]);

            #pragma unroll
            for (int c = 0; c < 8; c++) {
                const int cur = c & 3;
                if (c < 5) {
                    const int pb = (c + 3) & 3;
                    const int kn = kbase + (c + 3) * 8;
                    #pragma unroll
                    for (int i = 0; i < 8; i++)
                        hreg[pb][i] = __ldcg(&hsrc[(kn + i) * 32 + lane]);
                }
                const int kg0 = kbase + c * 8;
                #pragma unroll
                for (int kk = 0; kk < 8; kk += 2) {
                    const int kg = kg0 + kk;
                    float2 v0 = hreg[cur][kk];
                    float2 v1 = hreg[cur][kk + 1];
                    u64 dA0 = pack2(v0.x, v0.x);   // b = 2*lane,   k = kg
                    u64 dB0 = pack2(v0.y, v0.y);   // b = 2*lane+1, k = kg
                    u64 dA1 = pack2(v1.x, v1.x);   // b = 2*lane,   k = kg+1
                    u64 dB1 = pack2(v1.y, v1.y);   // b = 2*lane+1, k = kg+1
                    #pragma unroll
                    for (int st = 0; st < 8; st++) {
                        ulonglong2 wv = *(const ulonglong2*)&Ws[(st * 512 + kg) * 2];
                        acc[st][0] = fma2(dA0, wv.x, acc[st][0]);
                        acc[st][1] = fma2(dB0, wv.x, acc[st][1]);
                        acc[st][0] = fma2(dA1, wv.y, acc[st][0]);
                        acc[st][1] = fma2(dB1, wv.y, acc[st][1]);
                    }
                }
            }
        }

        // partials -> scratch [st][kr][b], one STS.128 per stream
        #pragma unroll
        for (int st = 0; st < 8; st++) {
            float2 p0 = *(float2*)&acc[st][0];
            float2 p1 = *(float2*)&acc[st][1];
            *(float4*)&scp[(st * 8 + wi) * 64 + 2 * lane] =
                make_float4(p0.x, p0.y, p1.x, p1.y);
        }
        __syncthreads();

        // cross-warp reduce (8 k-range partials) in packed f32x2 + gates
        float gt[4];
        #pragma unroll
        for (int g = 0; g < 4; g++) {
            int st = g * 2 + jp_r;
            const u64* rb = (const u64*)&scp[(st * 8) * 64 + b];
            u64 v0 = add2(rb[0 * 64], rb[1 * 64]);
            u64 v1 = add2(rb[2 * 64], rb[3 * 64]);
            u64 v2 = add2(rb[4 * 64], rb[5 * 64]);
            u64 v3 = add2(rb[6 * 64], rb[7 * 64]);
            float2 r = unpack2(add2(add2(v0, v1), add2(v2, v3)));
            gt[g] = (comp ? r.y : r.x) + xgv[g];
        }
        float ig = sigf(gt[0]), fg = sigf(gt[1]);
        float gg = tanh_f(gt[2]), og = sigf(gt[3]);
        c_reg = fg * c_reg + ig * gg;
        h_val = og * tanh_f(c_reg);

        __stcg(&g_h[s & 3][j * 64 + b], h_val);
        __syncthreads();   // all h stores of this CTA issued before flag bump
        if (tid == 0) {
            asm volatile("red.release.gpu.global.add.u32 [%0], %1;"
                         :: "l"(&g_wf[cta]), "r"(1u) : "memory");
        }
    }

    out[b * HH + j] = h_val;
    if (write_c) out[BB * HH + b * HH + j] = c_reg;
}

// ---------------------------------------------------------------------------
// kernel_launch
// ---------------------------------------------------------------------------
extern "C" void kernel_launch(void* const* d_in, const int* in_sizes, int n_in,
                              void* d_out, int out_size)
{
    const void*  seq = d_in[0];
    const float* emb = (const float*)d_in[1];
    const float* Wih = (const float*)d_in[2];
    const float* Whh = (const float*)d_in[3];
    const float* bih = (const float*)d_in[4];
    const float* bhh = (const float*)d_in[5];
    float* out = (float*)d_out;

    (void)in_sizes; (void)n_in;
    int write_c = (out_size >= 2 * BB * HH) ? 1 : 0;

    // 64 KB dynamic SMEM: W pairs 32K + scratch 32K
    static const int kSmem = (8192 + 8192) * (int)sizeof(float);
    cudaFuncSetAttribute(lstm_kernel, cudaFuncAttributeMaxDynamicSharedMemorySize, kSmem);

    xgates_gemm<<<dim3(GG / 64, SS / 2), 256>>>(seq, emb, Wih, bih, bhh);
    lstm_kernel<<<HH / 4, 256, kSmem>>>(Whh, out, write_c);
}